// round 1
// baseline (speedup 1.0000x reference)
#include <cuda_runtime.h>

// Problem constants (fixed shapes)
#define BDIM 32
#define NDIM 2048
#define HDIM 512
#define NCHUNK 16
#define CHUNK (NDIM / NCHUNK)   // 128
#define MASK_NEG 1e30f

// Scratch (device globals: allowed; no runtime allocation)
__device__ float g_alpha[BDIM * NDIM];               // masked attention logits
__device__ float g_part0[BDIM * NCHUNK * HDIM];      // partial y0 sums
__device__ float g_part1[BDIM * NCHUNK * HDIM];      // partial y1 sums
__device__ float g_y0T[HDIM * BDIM];                 // y0 transposed [h][b]
__device__ float g_y1T[HDIM * BDIM];                 // y1 transposed [h][b]
__device__ float g_qT [HDIM * BDIM];                 // Q  transposed [h][b]

// ---------------------------------------------------------------------------
// K1: alpha[b,n] = K[b,n,:] . wk  - (1-adj)*1e30
// (Q.wq + b_att is a per-row constant -> cancels in softmax, skipped)
// One warp per (b,n) row; 8 warps/block. Streams all of K (128 MiB).
// ---------------------------------------------------------------------------
__global__ __launch_bounds__(256)
void k_alpha(const float* __restrict__ Kmat,
             const float* __restrict__ w_att,
             const int*   __restrict__ adj)
{
    __shared__ float4 swk[HDIM / 4];
    int tid = threadIdx.x;
    if (tid < HDIM / 4)
        swk[tid] = ((const float4*)(w_att + HDIM))[tid];   // wk = w_att[0, H:2H]
    __syncthreads();

    int warp = tid >> 5, lane = tid & 31;
    int row  = blockIdx.x * 8 + warp;
    if (row >= BDIM * NDIM) return;

    const float4* kp = (const float4*)(Kmat + (size_t)row * HDIM);
    float acc = 0.f;
    #pragma unroll
    for (int i = 0; i < 4; i++) {
        float4 k4 = kp[lane + i * 32];
        float4 w4 = swk[lane + i * 32];
        acc += k4.x * w4.x + k4.y * w4.y + k4.z * w4.z + k4.w * w4.w;
    }
    #pragma unroll
    for (int o = 16; o > 0; o >>= 1)
        acc += __shfl_xor_sync(0xFFFFFFFFu, acc, o);

    if (lane == 0) {
        float adjf = (float)adj[row];
        g_alpha[row] = acc - (1.0f - adjf) * MASK_NEG;
    }
}

// ---------------------------------------------------------------------------
// K2: row softmax over N=2048, one block per b. Writes attn into d_out[0 .. B*N).
// ---------------------------------------------------------------------------
__global__ __launch_bounds__(1024)
void k_softmax(float* __restrict__ out_attn)
{
    __shared__ float sred[32];
    __shared__ float s_bm, s_bs;
    int b   = blockIdx.x;
    int tid = threadIdx.x;
    const float* a = g_alpha + b * NDIM;

    float v0 = a[tid], v1 = a[tid + 1024];

    // --- block max ---
    float m = fmaxf(v0, v1);
    #pragma unroll
    for (int o = 16; o > 0; o >>= 1)
        m = fmaxf(m, __shfl_xor_sync(0xFFFFFFFFu, m, o));
    if ((tid & 31) == 0) sred[tid >> 5] = m;
    __syncthreads();
    if (tid < 32) {
        float t = sred[tid];
        #pragma unroll
        for (int o = 16; o > 0; o >>= 1)
            t = fmaxf(t, __shfl_xor_sync(0xFFFFFFFFu, t, o));
        if (tid == 0) s_bm = t;
    }
    __syncthreads();
    m = s_bm;

    float e0 = __expf(v0 - m), e1 = __expf(v1 - m);

    // --- block sum ---
    float s = e0 + e1;
    #pragma unroll
    for (int o = 16; o > 0; o >>= 1)
        s += __shfl_xor_sync(0xFFFFFFFFu, s, o);
    __syncthreads();
    if ((tid & 31) == 0) sred[tid >> 5] = s;
    __syncthreads();
    if (tid < 32) {
        float t = sred[tid];
        #pragma unroll
        for (int o = 16; o > 0; o >>= 1)
            t += __shfl_xor_sync(0xFFFFFFFFu, t, o);
        if (tid == 0) s_bs = t;
    }
    __syncthreads();
    float inv = 1.0f / s_bs;

    out_attn[b * NDIM + tid]        = e0 * inv;
    out_attn[b * NDIM + tid + 1024] = e1 * inv;
}

// ---------------------------------------------------------------------------
// K3: partial weighted V sums. grid (NCHUNK, B), 512 threads (one per h).
// Streams all of V (128 MiB). Deterministic fixed-order accumulation.
// ---------------------------------------------------------------------------
__global__ __launch_bounds__(512)
void k_wsum(const float* __restrict__ V,
            const int*   __restrict__ s_mask,
            const float* __restrict__ attn)
{
    __shared__ float sw0[CHUNK];
    __shared__ float sw1[CHUNK];
    int c = blockIdx.x, b = blockIdx.y;
    int t = threadIdx.x;
    int n0 = c * CHUNK;

    if (t < CHUNK) {
        float w   = attn[b * NDIM + n0 + t];
        float smf = (float)s_mask[b * NDIM + n0 + t];
        float ws  = w * smf;
        sw0[t] = ws;
        sw1[t] = w - ws;
    }
    __syncthreads();

    const float* vp = V + ((size_t)b * NDIM + n0) * HDIM + t;
    float a0 = 0.f, a1 = 0.f;
    #pragma unroll 8
    for (int n = 0; n < CHUNK; n++) {
        float v = vp[(size_t)n * HDIM];
        a0 += sw0[n] * v;
        a1 += sw1[n] * v;
    }
    g_part0[(b * NCHUNK + c) * HDIM + t] = a0;
    g_part1[(b * NCHUNK + c) * HDIM + t] = a1;
}

// ---------------------------------------------------------------------------
// K4: reduce partials over chunks; store y0,y1,Q transposed to [h][b] so K5
// lanes (lane = b) read coalesced.
// ---------------------------------------------------------------------------
__global__ __launch_bounds__(512)
void k_reduce(const float* __restrict__ Q)
{
    int b = blockIdx.x;
    int h = threadIdx.x;
    float s0 = 0.f, s1 = 0.f;
    #pragma unroll
    for (int c = 0; c < NCHUNK; c++) {
        s0 += g_part0[(b * NCHUNK + c) * HDIM + h];
        s1 += g_part1[(b * NCHUNK + c) * HDIM + h];
    }
    g_y0T[h * BDIM + b] = s0;
    g_y1T[h * BDIM + b] = s1;
    g_qT [h * BDIM + b] = Q[b * HDIM + h];
}

// ---------------------------------------------------------------------------
// K5: attn_sum[b,o] = sum_h Wr0[o,h]*y0[b,h] + Wr1[o,h]*y1[b,h] + Wri[o,h]*Q[b,h]
// One warp per output column o (lane = b). W rows broadcast within warp and are
// read exactly once chip-wide (o-partitioned) -> total weight traffic = 3 MiB.
// ---------------------------------------------------------------------------
__global__ __launch_bounds__(256)
void k_final(const float* __restrict__ Wr0,
             const float* __restrict__ Wr1,
             const float* __restrict__ Wri,
             float* __restrict__ out)
{
    int warp = threadIdx.x >> 5, lane = threadIdx.x & 31;
    int o = blockIdx.x * 8 + warp;          // blockDim 256 -> 8 warps
    if (o >= HDIM) return;
    int b = lane;

    const float4* w0 = (const float4*)(Wr0 + (size_t)o * HDIM);
    const float4* w1 = (const float4*)(Wr1 + (size_t)o * HDIM);
    const float4* wi = (const float4*)(Wri + (size_t)o * HDIM);

    float acc = 0.f;
    #pragma unroll 4
    for (int h4 = 0; h4 < HDIM / 4; h4++) {
        float4 a = w0[h4];
        float4 c = w1[h4];
        float4 d = wi[h4];
        int h = h4 * 4;
        acc += a.x * g_y0T[(h + 0) * BDIM + b]
             + a.y * g_y0T[(h + 1) * BDIM + b]
             + a.z * g_y0T[(h + 2) * BDIM + b]
             + a.w * g_y0T[(h + 3) * BDIM + b];
        acc += c.x * g_y1T[(h + 0) * BDIM + b]
             + c.y * g_y1T[(h + 1) * BDIM + b]
             + c.z * g_y1T[(h + 2) * BDIM + b]
             + c.w * g_y1T[(h + 3) * BDIM + b];
        acc += d.x * g_qT[(h + 0) * BDIM + b]
             + d.y * g_qT[(h + 1) * BDIM + b]
             + d.z * g_qT[(h + 2) * BDIM + b]
             + d.w * g_qT[(h + 3) * BDIM + b];
    }
    out[BDIM * NDIM + b * HDIM + o] = acc;
}

// ---------------------------------------------------------------------------
// Launch. Inputs (metadata order): Q, K, V, adj, s_mask, w_att, b_att,
// Wr0, Wr1, Wri. Output: [attn (B*N) | attn_sum (B*H)] floats.
// ---------------------------------------------------------------------------
extern "C" void kernel_launch(void* const* d_in, const int* in_sizes, int n_in,
                              void* d_out, int out_size)
{
    const float* Q      = (const float*)d_in[0];
    const float* Kmat   = (const float*)d_in[1];
    const float* V      = (const float*)d_in[2];
    const int*   adj    = (const int*)  d_in[3];
    const int*   s_mask = (const int*)  d_in[4];
    const float* w_att  = (const float*)d_in[5];
    // d_in[6] = b_att (cancels in softmax; unused)
    const float* Wr0    = (const float*)d_in[7];
    const float* Wr1    = (const float*)d_in[8];
    const float* Wri    = (const float*)d_in[9];
    float* out = (float*)d_out;

    // K1: alpha over all (b,n) rows, one warp per row
    k_alpha<<<(BDIM * NDIM) / 8, 256>>>(Kmat, w_att, adj);

    // K2: softmax per batch row, attn -> out[0 .. B*N)
    k_softmax<<<BDIM, 1024>>>(out);

    // K3: partial weighted V sums
    dim3 g3(NCHUNK, BDIM);
    k_wsum<<<g3, 512>>>(V, s_mask, out);

    // K4: chunk reduce + transpose
    k_reduce<<<BDIM, 512>>>(Q);

    // K5: final mini-GEMM -> out[B*N .. B*N + B*H)
    k_final<<<HDIM / 8, 256>>>(Wr0, Wr1, Wri, out);
}